// round 5
// baseline (speedup 1.0000x reference)
#include <cuda_runtime.h>
#include <cstdint>
#include <cstddef>

#define MAXN 100000
#define D 64

// Scratch (no allocations allowed): 25.6MB + 0.8MB
__device__ float g_xws[(size_t)MAXN * D];   // dinv[n] * (x[n] @ W)
__device__ float g_deg[MAXN];
__device__ float g_dinv[MAXN];

typedef unsigned long long ull;

__device__ __forceinline__ ull fma2(ull a, ull b, ull c) {
    ull d;
    asm("fma.rn.f32x2 %0, %1, %2, %3;" : "=l"(d) : "l"(a), "l"(b), "l"(c));
    return d;
}
__device__ __forceinline__ ull mul2(ull a, ull b) {
    ull d;
    asm("mul.rn.f32x2 %0, %1, %2;" : "=l"(d) : "l"(a), "l"(b));
    return d;
}
__device__ __forceinline__ ull pack2(float lo, float hi) {
    ull d;
    asm("mov.b64 %0, {%1, %2};" : "=l"(d) : "r"(__float_as_uint(lo)), "r"(__float_as_uint(hi)));
    return d;
}
__device__ __forceinline__ void unpack2(ull v, float& lo, float& hi) {
    unsigned int l, h;
    asm("mov.b64 {%0, %1}, %2;" : "=r"(l), "=r"(h) : "l"(v));
    lo = __uint_as_float(l); hi = __uint_as_float(h);
}

// ---------------------------------------------------------------------------
// K1: zero the accumulator (d_out) and init deg = 1 (self loop)
// ---------------------------------------------------------------------------
__global__ void k_init(float4* __restrict__ out4, int n_out4, int N) {
    int i = blockIdx.x * blockDim.x + threadIdx.x;
    int stride = gridDim.x * blockDim.x;
    float4 z = make_float4(0.f, 0.f, 0.f, 0.f);
    for (int idx = i; idx < n_out4; idx += stride) out4[idx] = z;
    for (int idx = i; idx < N; idx += stride) g_deg[idx] = 1.0f;
}

// ---------------------------------------------------------------------------
// K2: degree over destinations (col = edge_index[1]).  edge_index is INT32
// (JAX x64 is disabled; the "int64" array is silently int32).
// ---------------------------------------------------------------------------
__global__ void k_deg(const int* __restrict__ ei, int E) {
    int e = blockIdx.x * blockDim.x + threadIdx.x;
    if (e < E) {
        int c = ei[E + e];
        atomicAdd(&g_deg[c], 1.0f);   // no return use -> RED
    }
}

// ---------------------------------------------------------------------------
// K3: g_xws[n] = rsqrt(deg[n]) * (x[n] @ W), also store g_dinv.
// Block = 256 threads handles 256 rows. Thread (rg = tid>>4, cg = tid&15)
// computes a 16-row x 4-col tile using packed fma.rn.f32x2 (rows paired).
// Dynamic smem: xs transposed [64][256] (64KB) + W duplicated into two
// bank-uniform float4 tables wdA/wdB [64][16] float4 (16KB each).
// ---------------------------------------------------------------------------
__global__ void __launch_bounds__(256, 2) k_xw(const float* __restrict__ x,
                                               const float* __restrict__ W,
                                               int N) {
    extern __shared__ float sm[];
    float* xs  = sm;                 // [k][row] : k*256 + row  (row pairs -> float2)
    float* wdA = sm + 64 * 256;      // [k][cg] float4 {w(4cg)dup, w(4cg+1)dup}
    float* wdB = wdA + 64 * 64;      // [k][cg] float4 {w(4cg+2)dup, w(4cg+3)dup}

    int tid = threadIdx.x;
    int R0  = blockIdx.x * 256;

    // Load W duplicated
    for (int i = tid; i < 64 * 64; i += 256) {
        int k = i >> 6, c = i & 63;
        int cg = c >> 2, s = c & 3;
        float w = W[i];
        float* dst = ((s < 2) ? wdA : wdB) + ((k * 16 + cg) * 4 + (s & 1) * 2);
        dst[0] = w; dst[1] = w;
    }
    // Load x tile transposed: xs[k*256 + row_local]
    for (int i = tid; i < 256 * 16; i += 256) {
        int row = i >> 4;       // local row 0..255
        int kq  = i & 15;       // quad of k
        int grow = R0 + row;
        float4 v = (grow < N) ? ((const float4*)x)[(size_t)grow * 16 + kq]
                              : make_float4(0.f, 0.f, 0.f, 0.f);
        int base = (kq * 4) * 256 + row;
        xs[base]       = v.x;
        xs[base + 256] = v.y;
        xs[base + 512] = v.z;
        xs[base + 768] = v.w;
    }
    __syncthreads();

    int cg = tid & 15;
    int rg = tid >> 4;

    ull acc[8][4];
#pragma unroll
    for (int i = 0; i < 8; ++i)
#pragma unroll
        for (int c = 0; c < 4; ++c) acc[i][c] = 0ULL;

    const float* xrow = xs + rg * 16;

#pragma unroll 8
    for (int k = 0; k < 64; ++k) {
        ulonglong2 wA = *(const ulonglong2*)(wdA + (k * 16 + cg) * 4);
        ulonglong2 wB = *(const ulonglong2*)(wdB + (k * 16 + cg) * 4);
        const float* xk = xrow + k * 256;
#pragma unroll
        for (int i = 0; i < 8; ++i) {
            ull xv = *(const ull*)(xk + 2 * i);
            acc[i][0] = fma2(xv, wA.x, acc[i][0]);
            acc[i][1] = fma2(xv, wA.y, acc[i][1]);
            acc[i][2] = fma2(xv, wB.x, acc[i][2]);
            acc[i][3] = fma2(xv, wB.y, acc[i][3]);
        }
    }

    // Epilogue: scale by rsqrt(deg) and store
    int rbase = R0 + rg * 16;
#pragma unroll
    for (int i = 0; i < 8; ++i) {
        int r0 = rbase + 2 * i;
        if (r0 >= N) break;
        bool has1 = (r0 + 1 < N);
        float s0 = rsqrtf(g_deg[r0]);
        float s1 = has1 ? rsqrtf(g_deg[r0 + 1]) : 0.f;
        if (cg == 0) {
            g_dinv[r0] = s0;
            if (has1) g_dinv[r0 + 1] = s1;
        }
        ull sv = pack2(s0, s1);
        float4 lo4, hi4;
        ull m0 = mul2(acc[i][0], sv);
        ull m1 = mul2(acc[i][1], sv);
        ull m2 = mul2(acc[i][2], sv);
        ull m3 = mul2(acc[i][3], sv);
        unpack2(m0, lo4.x, hi4.x);
        unpack2(m1, lo4.y, hi4.y);
        unpack2(m2, lo4.z, hi4.z);
        unpack2(m3, lo4.w, hi4.w);
        *(float4*)(g_xws + (size_t)r0 * 64 + cg * 4) = lo4;
        if (has1)
            *(float4*)(g_xws + (size_t)(r0 + 1) * 64 + cg * 4) = hi4;
    }
}

// ---------------------------------------------------------------------------
// K4: scatter-add. 16 threads per edge, one float4 gather each, 4 scalar
// RED.F32 to L2.  edge_index is int32.
// ---------------------------------------------------------------------------
__global__ void k_scatter(const int* __restrict__ ei,
                          float* __restrict__ out, int E) {
    int t = blockIdx.x * blockDim.x + threadIdx.x;
    int e = t >> 4;
    if (e >= E) return;
    int j = t & 15;
    int r = __ldg(&ei[e]);
    int c = __ldg(&ei[E + e]);
    float4 v = *(const float4*)(g_xws + (size_t)r * 64 + j * 4);
    float* dst = out + (size_t)c * 64 + j * 4;
    atomicAdd(dst + 0, v.x);
    atomicAdd(dst + 1, v.y);
    atomicAdd(dst + 2, v.z);
    atomicAdd(dst + 3, v.w);
}

// ---------------------------------------------------------------------------
// K5: out = relu(dinv * (acc + xws) + b)   (xws term = self loop)
// ---------------------------------------------------------------------------
__global__ void k_final(float* __restrict__ out, const float* __restrict__ b,
                        int N) {
    int i = blockIdx.x * blockDim.x + threadIdx.x;  // one float4 each
    int total = N * 16;
    if (i >= total) return;
    int n  = i >> 4;
    int jq = i & 15;
    float s = g_dinv[n];
    float4 a  = ((const float4*)out)[i];
    float4 w  = ((const float4*)g_xws)[i];
    float4 bb = ((const float4*)b)[jq];
    float4 r;
    r.x = fmaxf(fmaf(s, a.x + w.x, bb.x), 0.f);
    r.y = fmaxf(fmaf(s, a.y + w.y, bb.y), 0.f);
    r.z = fmaxf(fmaf(s, a.z + w.z, bb.z), 0.f);
    r.w = fmaxf(fmaf(s, a.w + w.w, bb.w), 0.f);
    ((float4*)out)[i] = r;
}

// ---------------------------------------------------------------------------
extern "C" void kernel_launch(void* const* d_in, const int* in_sizes, int n_in,
                              void* d_out, int out_size) {
    const float* x  = (const float*)d_in[0];
    const int*   ei = (const int*)d_in[1];     // int32! (JAX x64 disabled)
    const float* W  = (const float*)d_in[2];
    const float* b  = (const float*)d_in[3];
    float*       out = (float*)d_out;

    int N = in_sizes[0] / 64;
    int E = in_sizes[1] / 2;

    static const int SMEM_XW = (64 * 256 + 2 * 64 * 64) * 4;  // 96 KB
    cudaFuncSetAttribute(k_xw, cudaFuncAttributeMaxDynamicSharedMemorySize,
                         SMEM_XW);

    k_init<<<2048, 256>>>((float4*)out, N * 16, N);
    k_deg<<<(E + 255) / 256, 256>>>(ei, E);
    k_xw<<<(N + 255) / 256, 256, SMEM_XW>>>(x, W, N);
    // 16 threads per edge
    k_scatter<<<((size_t)E * 16 + 255) / 256, 256>>>(ei, out, E);
    k_final<<<(N * 16 + 255) / 256, 256>>>(out, b, N);
}

// round 6
// speedup vs baseline: 1.8519x; 1.8519x over previous
#include <cuda_runtime.h>
#include <cstdint>
#include <cstddef>

#define MAXN 100000
#define D 64

// Scratch (no allocations allowed): 25.6MB + 0.8MB
__device__ float g_xws[(size_t)MAXN * D];   // dinv[n] * (x[n] @ W)
__device__ float g_deg[MAXN];
__device__ float g_dinv[MAXN];

typedef unsigned long long ull;

__device__ __forceinline__ ull fma2(ull a, ull b, ull c) {
    ull d;
    asm("fma.rn.f32x2 %0, %1, %2, %3;" : "=l"(d) : "l"(a), "l"(b), "l"(c));
    return d;
}
__device__ __forceinline__ ull mul2(ull a, ull b) {
    ull d;
    asm("mul.rn.f32x2 %0, %1, %2;" : "=l"(d) : "l"(a), "l"(b));
    return d;
}
__device__ __forceinline__ ull pack2(float lo, float hi) {
    ull d;
    asm("mov.b64 %0, {%1, %2};" : "=l"(d) : "r"(__float_as_uint(lo)), "r"(__float_as_uint(hi)));
    return d;
}
__device__ __forceinline__ void unpack2(ull v, float& lo, float& hi) {
    unsigned int l, h;
    asm("mov.b64 {%0, %1}, %2;" : "=r"(l), "=r"(h) : "l"(v));
    lo = __uint_as_float(l); hi = __uint_as_float(h);
}

// ---------------------------------------------------------------------------
// K1: zero the accumulator (d_out) and init deg = 1 (self loop)
// ---------------------------------------------------------------------------
__global__ void k_init(float4* __restrict__ out4, int n_out4, int N) {
    int i = blockIdx.x * blockDim.x + threadIdx.x;
    int stride = gridDim.x * blockDim.x;
    float4 z = make_float4(0.f, 0.f, 0.f, 0.f);
    for (int idx = i; idx < n_out4; idx += stride) out4[idx] = z;
    for (int idx = i; idx < N; idx += stride) g_deg[idx] = 1.0f;
}

// ---------------------------------------------------------------------------
// K2: degree over destinations (col = edge_index[1]).  edge_index is INT32.
// ---------------------------------------------------------------------------
__global__ void k_deg(const int* __restrict__ ei, int E) {
    int e = blockIdx.x * blockDim.x + threadIdx.x;
    if (e < E) {
        int c = ei[E + e];
        atomicAdd(&g_deg[c], 1.0f);   // no return use -> RED
    }
}

// ---------------------------------------------------------------------------
// K3: g_xws[n] = rsqrt(deg[n]) * (x[n] @ W), also store g_dinv.
// Block = 256 threads handles 256 rows. Thread (rg = tid>>4, cg = tid&15)
// computes a 16-row x 4-col tile using packed fma.rn.f32x2 (rows paired).
// ---------------------------------------------------------------------------
__global__ void __launch_bounds__(256, 2) k_xw(const float* __restrict__ x,
                                               const float* __restrict__ W,
                                               int N) {
    extern __shared__ float sm[];
    float* xs  = sm;                 // [k][row] : k*256 + row  (row pairs -> float2)
    float* wdA = sm + 64 * 256;      // [k][cg] float4 {w(4cg)dup, w(4cg+1)dup}
    float* wdB = wdA + 64 * 64;      // [k][cg] float4 {w(4cg+2)dup, w(4cg+3)dup}

    int tid = threadIdx.x;
    int R0  = blockIdx.x * 256;

    // Load W duplicated
    for (int i = tid; i < 64 * 64; i += 256) {
        int k = i >> 6, c = i & 63;
        int cg = c >> 2, s = c & 3;
        float w = W[i];
        float* dst = ((s < 2) ? wdA : wdB) + ((k * 16 + cg) * 4 + (s & 1) * 2);
        dst[0] = w; dst[1] = w;
    }
    // Load x tile transposed: xs[k*256 + row_local]
    for (int i = tid; i < 256 * 16; i += 256) {
        int row = i >> 4;       // local row 0..255
        int kq  = i & 15;       // quad of k
        int grow = R0 + row;
        float4 v = (grow < N) ? ((const float4*)x)[(size_t)grow * 16 + kq]
                              : make_float4(0.f, 0.f, 0.f, 0.f);
        int base = (kq * 4) * 256 + row;
        xs[base]       = v.x;
        xs[base + 256] = v.y;
        xs[base + 512] = v.z;
        xs[base + 768] = v.w;
    }
    __syncthreads();

    int cg = tid & 15;
    int rg = tid >> 4;

    ull acc[8][4];
#pragma unroll
    for (int i = 0; i < 8; ++i)
#pragma unroll
        for (int c = 0; c < 4; ++c) acc[i][c] = 0ULL;

    const float* xrow = xs + rg * 16;

#pragma unroll 8
    for (int k = 0; k < 64; ++k) {
        ulonglong2 wA = *(const ulonglong2*)(wdA + (k * 16 + cg) * 4);
        ulonglong2 wB = *(const ulonglong2*)(wdB + (k * 16 + cg) * 4);
        const float* xk = xrow + k * 256;
#pragma unroll
        for (int i = 0; i < 8; ++i) {
            ull xv = *(const ull*)(xk + 2 * i);
            acc[i][0] = fma2(xv, wA.x, acc[i][0]);
            acc[i][1] = fma2(xv, wA.y, acc[i][1]);
            acc[i][2] = fma2(xv, wB.x, acc[i][2]);
            acc[i][3] = fma2(xv, wB.y, acc[i][3]);
        }
    }

    // Epilogue: scale by rsqrt(deg) and store
    int rbase = R0 + rg * 16;
#pragma unroll
    for (int i = 0; i < 8; ++i) {
        int r0 = rbase + 2 * i;
        if (r0 >= N) break;
        bool has1 = (r0 + 1 < N);
        float s0 = rsqrtf(g_deg[r0]);
        float s1 = has1 ? rsqrtf(g_deg[r0 + 1]) : 0.f;
        if (cg == 0) {
            g_dinv[r0] = s0;
            if (has1) g_dinv[r0 + 1] = s1;
        }
        ull sv = pack2(s0, s1);
        float4 lo4, hi4;
        ull m0 = mul2(acc[i][0], sv);
        ull m1 = mul2(acc[i][1], sv);
        ull m2 = mul2(acc[i][2], sv);
        ull m3 = mul2(acc[i][3], sv);
        unpack2(m0, lo4.x, hi4.x);
        unpack2(m1, lo4.y, hi4.y);
        unpack2(m2, lo4.z, hi4.z);
        unpack2(m3, lo4.w, hi4.w);
        *(float4*)(g_xws + (size_t)r0 * 64 + cg * 4) = lo4;
        if (has1)
            *(float4*)(g_xws + (size_t)(r0 + 1) * 64 + cg * 4) = hi4;
    }
}

// ---------------------------------------------------------------------------
// K4: scatter-add. 16 threads per edge, one float4 gather each, one
// red.global.add.v4.f32 (sm_90+; the R0 trap was the int64 index bug,
// not this instruction).
// ---------------------------------------------------------------------------
__global__ void k_scatter(const int* __restrict__ ei,
                          float* __restrict__ out, int E) {
    int t = blockIdx.x * blockDim.x + threadIdx.x;
    int e = t >> 4;
    if (e >= E) return;
    int j = t & 15;
    int r = __ldg(&ei[e]);
    int c = __ldg(&ei[E + e]);
    float4 v = *(const float4*)(g_xws + (size_t)r * 64 + j * 4);
    float* dst = out + (size_t)c * 64 + j * 4;
    asm volatile("red.global.add.v4.f32 [%0], {%1, %2, %3, %4};"
                 :: "l"(dst), "f"(v.x), "f"(v.y), "f"(v.z), "f"(v.w)
                 : "memory");
}

// ---------------------------------------------------------------------------
// K5: out = relu(dinv * (acc + xws) + b)   (xws term = self loop)
// ---------------------------------------------------------------------------
__global__ void k_final(float* __restrict__ out, const float* __restrict__ b,
                        int N) {
    int i = blockIdx.x * blockDim.x + threadIdx.x;  // one float4 each
    int total = N * 16;
    if (i >= total) return;
    int n  = i >> 4;
    int jq = i & 15;
    float s = g_dinv[n];
    float4 a  = ((const float4*)out)[i];
    float4 w  = ((const float4*)g_xws)[i];
    float4 bb = ((const float4*)b)[jq];
    float4 r;
    r.x = fmaxf(fmaf(s, a.x + w.x, bb.x), 0.f);
    r.y = fmaxf(fmaf(s, a.y + w.y, bb.y), 0.f);
    r.z = fmaxf(fmaf(s, a.z + w.z, bb.z), 0.f);
    r.w = fmaxf(fmaf(s, a.w + w.w, bb.w), 0.f);
    ((float4*)out)[i] = r;
}

// ---------------------------------------------------------------------------
extern "C" void kernel_launch(void* const* d_in, const int* in_sizes, int n_in,
                              void* d_out, int out_size) {
    const float* x  = (const float*)d_in[0];
    const int*   ei = (const int*)d_in[1];     // int32! (JAX x64 disabled)
    const float* W  = (const float*)d_in[2];
    const float* b  = (const float*)d_in[3];
    float*       out = (float*)d_out;

    int N = in_sizes[0] / 64;
    int E = in_sizes[1] / 2;

    static const int SMEM_XW = (64 * 256 + 2 * 64 * 64) * 4;  // 96 KB
    cudaFuncSetAttribute(k_xw, cudaFuncAttributeMaxDynamicSharedMemorySize,
                         SMEM_XW);

    k_init<<<2048, 256>>>((float4*)out, N * 16, N);
    k_deg<<<(E + 255) / 256, 256>>>(ei, E);
    k_xw<<<(N + 255) / 256, 256, SMEM_XW>>>(x, W, N);
    // 16 threads per edge
    k_scatter<<<((size_t)E * 16 + 255) / 256, 256>>>(ei, out, E);
    k_final<<<(N * 16 + 255) / 256, 256>>>(out, b, N);
}